// round 7
// baseline (speedup 1.0000x reference)
#include <cuda_runtime.h>
#include <cuda_bf16.h>
#include <stdint.h>
#include <math.h>

#define NBATCH 4
#define SQ    2048
#define SKV   4096
#define EDIM  1024
#define CDIM  512
#define HEADS 16
#define HDIM  64

// ---------------------------------------------------------------------------
// Static device scratch. Split operands stored [hi | lo] (width 2K).
// Logical GEMM runs K3=3K with per-chunk source remap:
//   A terms: hi, hi, lo     B terms: hi, lo, hi
// => sum = A0B0 + A0B1 + A1B0  (Markidis split, err ~2^-18)
// ---------------------------------------------------------------------------
__device__ float         g_cond[(size_t)NBATCH * SQ * EDIM];
__device__ __nv_bfloat16 g_condext[(size_t)NBATCH * SQ * 2 * CDIM];
__device__ __nv_bfloat16 g_wcext[(size_t)EDIM * 2 * CDIM];
__device__ __nv_bfloat16 g_woext[(size_t)EDIM * 2 * EDIM];
__device__ __nv_bfloat16 g_aoext[(size_t)NBATCH * SKV * 2 * EDIM];

// ---------------------------------------------------------------------------
// PTX helpers
// ---------------------------------------------------------------------------
__device__ __forceinline__ uint32_t smem_u32(const void* p) {
    uint32_t a;
    asm("{ .reg .u64 t; cvta.to.shared.u64 t, %1; cvt.u32.u64 %0, t; }"
        : "=r"(a) : "l"(p));
    return a;
}

__device__ __forceinline__ void cp16(uint32_t dst, const void* src) {
    asm volatile("cp.async.cg.shared.global [%0], [%1], 16;\n" :: "r"(dst), "l"(src));
}

#define LDSM4(r, addr) \
    asm volatile("ldmatrix.sync.aligned.m8n8.x4.shared.b16 {%0,%1,%2,%3}, [%4];" \
        : "=r"((r)[0]), "=r"((r)[1]), "=r"((r)[2]), "=r"((r)[3]) : "r"(addr))

#define MMA16816(d, a, b) \
    asm volatile("mma.sync.aligned.m16n8k16.row.col.f32.bf16.bf16.f32 " \
        "{%0,%1,%2,%3}, {%4,%5,%6,%7}, {%8,%9}, {%0,%1,%2,%3};" \
        : "+f"((d)[0]), "+f"((d)[1]), "+f"((d)[2]), "+f"((d)[3]) \
        : "r"((a)[0]), "r"((a)[1]), "r"((a)[2]), "r"((a)[3]), \
          "r"((b)[0]), "r"((b)[1]))

// ---------------------------------------------------------------------------
// split: fp32 (M,K) -> bf16 (M,2K) as [hi | lo]
// ---------------------------------------------------------------------------
__global__ __launch_bounds__(256) void split_pack(
    const float* __restrict__ src, __nv_bfloat16* __restrict__ dst,
    int K, int n)
{
    int i = (blockIdx.x * blockDim.x + threadIdx.x) * 4;
    if (i >= n) return;
    int m = i / K, k = i % K;
    float4 v = *(const float4*)(src + i);
    float x[4] = {v.x, v.y, v.z, v.w};
    __nv_bfloat16 hi[4], lo[4];
    #pragma unroll
    for (int j = 0; j < 4; j++) {
        hi[j] = __float2bfloat16_rn(x[j]);
        lo[j] = __float2bfloat16_rn(x[j] - __bfloat162float(hi[j]));
    }
    size_t base = (size_t)m * 2 * K + k;
    *(uint2*)(dst + base)     = *(uint2*)hi;
    *(uint2*)(dst + base + K) = *(uint2*)lo;
}

// ---------------------------------------------------------------------------
// HMMA GEMM. BM=BN=128, BKC=64, 8 warps (32x64 warp tile), 4-stage cp.async,
// register double-buffered fragments (LDSM for ks+1 overlaps MMA for ks).
// SMEM rows 144B: stride 36 words == 4 mod 32 -> conflict-free ldmatrix.
// 147KB smem -> 1 CTA/SM, regs free to ~180.
// ---------------------------------------------------------------------------
#define BM 128
#define BN 128
#define BKC 64
#define AROW 144
#define ASTAGE (128 * AROW)       // 18432 B
#define STAGE  (2 * ASTAGE)       // 36864 B
#define NSTAGE 4
#define DSMEM  (NSTAGE * STAGE)   // 147456 B

__device__ __forceinline__ void gemm_issue(
    uint32_t s0, int slot, int c, int nc1, int K, int tid, int mBase, int nBase,
    const __nv_bfloat16* __restrict__ A, const __nv_bfloat16* __restrict__ B)
{
    // term schedule: A: hi,hi,lo   B: hi,lo,hi
    int k0A, k0B;
    if (c < nc1)          { k0A = c * BKC;                 k0B = c * BKC; }
    else if (c < 2 * nc1) { k0A = (c - nc1) * BKC;         k0B = K + (c - nc1) * BKC; }
    else                  { k0A = K + (c - 2 * nc1) * BKC; k0B = (c - 2 * nc1) * BKC; }

    const int K2 = 2 * K;
    uint32_t sA = s0 + slot * STAGE;
    uint32_t sB = sA + ASTAGE;
    #pragma unroll
    for (int i = 0; i < 4; i++) {
        int ch = tid + i * 256;          // 0..1023
        int r = ch >> 3, col = ch & 7;   // row, 16B-chunk within 128B
        cp16(sA + r * AROW + col * 16, A + (size_t)(mBase + r) * K2 + k0A + col * 8);
        cp16(sB + r * AROW + col * 16, B + (size_t)(nBase + r) * K2 + k0B + col * 8);
    }
    asm volatile("cp.async.commit_group;");
}

__device__ __forceinline__ void load_frags(
    uint32_t sA, uint32_t sB, int ks, int wm, int wn, int lane,
    uint32_t af[2][4], uint32_t bf[8][2])
{
    #pragma unroll
    for (int mi = 0; mi < 2; mi++) {
        uint32_t addr = sA + (wm + mi * 16 + (lane & 15)) * AROW
                      + ks * 32 + (lane >> 4) * 16;
        LDSM4(af[mi], addr);
    }
    #pragma unroll
    for (int p = 0; p < 4; p++) {
        int grp = lane >> 3, w = lane & 7;
        int nsel = p * 2 + (grp >> 1);
        uint32_t addr = sB + (wn + nsel * 8 + w) * AROW
                      + ks * 32 + (grp & 1) * 16;
        uint32_t r[4];
        LDSM4(r, addr);
        bf[p * 2][0]     = r[0];
        bf[p * 2][1]     = r[1];
        bf[p * 2 + 1][0] = r[2];
        bf[p * 2 + 1][1] = r[3];
    }
}

__global__ __launch_bounds__(256) void gemm_hmma(
    const __nv_bfloat16* __restrict__ A, const __nv_bfloat16* __restrict__ B,
    const float* __restrict__ bias, float* __restrict__ C,
    int M, int N, int K)
{
    extern __shared__ char smem[];
    const int tid  = threadIdx.x;
    const int wid  = tid >> 5;
    const int lane = tid & 31;
    const int mBase = blockIdx.y * BM;
    const int nBase = blockIdx.x * BN;
    const int wm = (wid & 3) * 32;
    const int wn = (wid >> 2) * 64;

    const uint32_t s0 = smem_u32(smem);
    const int nc1 = K / BKC;
    const int NC = 3 * nc1;

    float acc[2][8][4];
    #pragma unroll
    for (int i = 0; i < 2; i++)
        #pragma unroll
        for (int j = 0; j < 8; j++)
            #pragma unroll
            for (int q = 0; q < 4; q++) acc[i][j][q] = 0.f;

    // prologue: NSTAGE-1 stages in flight, then first fragment set
    gemm_issue(s0, 0, 0, nc1, K, tid, mBase, nBase, A, B);
    gemm_issue(s0, 1, 1, nc1, K, tid, mBase, nBase, A, B);
    gemm_issue(s0, 2, 2, nc1, K, tid, mBase, nBase, A, B);
    asm volatile("cp.async.wait_group 2;");
    __syncthreads();

    uint32_t af[2][2][4];
    uint32_t bf[2][8][2];
    load_frags(s0, s0 + ASTAGE, 0, wm, wn, lane, af[0], bf[0]);

    int buf = 0;
    for (int c = 0; c < NC; c++) {
        uint32_t csA = s0 + (c % NSTAGE) * STAGE;
        uint32_t csB = csA + ASTAGE;
        #pragma unroll
        for (int ks = 0; ks < 4; ks++) {
            int nb = buf ^ 1;
            if (ks < 3) {
                load_frags(csA, csB, ks + 1, wm, wn, lane, af[nb], bf[nb]);
            } else {
                if (c + 3 < NC)
                    gemm_issue(s0, (c + 3) % NSTAGE, c + 3, nc1, K, tid,
                               mBase, nBase, A, B);
                else
                    asm volatile("cp.async.commit_group;");
                if (c + 1 < NC) {
                    asm volatile("cp.async.wait_group 2;");
                    __syncthreads();
                    uint32_t nA = s0 + ((c + 1) % NSTAGE) * STAGE;
                    load_frags(nA, nA + ASTAGE, 0, wm, wn, lane, af[nb], bf[nb]);
                }
            }
            #pragma unroll
            for (int mi = 0; mi < 2; mi++)
                #pragma unroll
                for (int ni = 0; ni < 8; ni++)
                    MMA16816(acc[mi][ni], af[buf][mi], bf[buf][ni]);
            buf = nb;
        }
    }

    const int g = lane >> 2, tg = lane & 3;
    #pragma unroll
    for (int mi = 0; mi < 2; mi++) {
        int row0 = mBase + wm + mi * 16 + g;
        #pragma unroll
        for (int ni = 0; ni < 8; ni++) {
            int col = nBase + wn + ni * 8 + tg * 2;
            float b0 = __ldg(bias + col), b1 = __ldg(bias + col + 1);
            float2 v0 = make_float2(acc[mi][ni][0] + b0, acc[mi][ni][1] + b1);
            float2 v1 = make_float2(acc[mi][ni][2] + b0, acc[mi][ni][3] + b1);
            *(float2*)(C + (size_t)row0 * N + col) = v0;
            *(float2*)(C + (size_t)(row0 + 8) * N + col) = v1;
        }
    }
}

// ---------------------------------------------------------------------------
// Per-position heads-attention (fp32 exact). Writes bf16 [hi | lo] rows.
// ---------------------------------------------------------------------------
__global__ __launch_bounds__(256) void attn_kernel(
    const float* __restrict__ queries, const float* __restrict__ keys,
    const float* __restrict__ values, const int* __restrict__ mask)
{
    __shared__ float cq[1024];
    __shared__ float kT[64 * 17];
    __shared__ float vv[1024];
    __shared__ float sc[16][16];

    const int pos = blockIdx.x;
    const int n = pos >> 12;
    const int t = pos & (SKV - 1);
    const int tid = threadIdx.x;

    const float* cqrow = (t & 1)
        ? (g_cond  + (size_t)(n * SQ + (t >> 1)) * EDIM)
        : (queries + (size_t)(n * SQ + (t >> 1)) * EDIM);
    const float* krow = keys   + (size_t)pos * EDIM;
    const float* vrow = values + (size_t)pos * EDIM;

    ((float4*)cq)[tid] = ((const float4*)cqrow)[tid];
    ((float4*)vv)[tid] = ((const float4*)vrow)[tid];
    {
        float4 kv = ((const float4*)krow)[tid];
        int gidx = tid * 4;
        #pragma unroll
        for (int i = 0; i < 4; i++) {
            int gg = gidx + i;
            kT[(gg & 63) * 17 + (gg >> 6)] = (&kv.x)[i];
        }
    }
    __syncthreads();

    const int h = tid >> 4;
    const int e = tid & 15;
    float s = 0.f;
    #pragma unroll
    for (int d = 0; d < HDIM; d++)
        s += cq[h * HDIM + d] * kT[d * 17 + e];
    s *= 0.125f;

    if (mask[(size_t)pos * (HEADS * HEADS) + h * 16 + e] == 0) s = -1e20f;
    sc[h][e] = s;
    __syncthreads();

    float mx = -INFINITY;
    #pragma unroll
    for (int j = 0; j < 16; j++) mx = fmaxf(mx, sc[h][j]);
    float denom = 0.f;
    #pragma unroll
    for (int j = 0; j < 16; j++) denom += expf(sc[h][j] - mx);
    float p = expf(s - mx) / denom;
    __syncthreads();
    sc[h][e] = p;
    __syncthreads();

    const int obase = tid * 4;
    const int oh = obase >> 6;
    const int od = obase & 63;
    float a0 = 0.f, a1 = 0.f, a2 = 0.f, a3 = 0.f;
    #pragma unroll
    for (int j = 0; j < 16; j++) {
        float a = sc[oh][j];
        const float* vj = vv + j * HDIM + od;
        a0 += a * vj[0];
        a1 += a * vj[1];
        a2 += a * vj[2];
        a3 += a * vj[3];
    }

    float o[4] = {a0, a1, a2, a3};
    __nv_bfloat16 hi[4], lo[4];
    #pragma unroll
    for (int j = 0; j < 4; j++) {
        hi[j] = __float2bfloat16_rn(o[j]);
        lo[j] = __float2bfloat16_rn(o[j] - __bfloat162float(hi[j]));
    }
    size_t base = (size_t)pos * (2 * EDIM) + obase;
    *(uint2*)(g_aoext + base)        = *(uint2*)hi;
    *(uint2*)(g_aoext + base + EDIM) = *(uint2*)lo;
}

// ---------------------------------------------------------------------------
// Launch
// ---------------------------------------------------------------------------
extern "C" void kernel_launch(void* const* d_in, const int* in_sizes, int n_in,
                              void* d_out, int out_size)
{
    const float* values    = (const float*)d_in[0];
    const float* keys      = (const float*)d_in[1];
    const float* queries   = (const float*)d_in[2];
    const int*   mask      = (const int*)  d_in[3];
    const float* condition = (const float*)d_in[4];
    const float* Wc        = (const float*)d_in[5];
    const float* bc        = (const float*)d_in[6];
    const float* Wo        = (const float*)d_in[7];
    const float* bo        = (const float*)d_in[8];
    float* out = (float*)d_out;

    float* cond_ptr;
    __nv_bfloat16 *cext, *wcext, *woext, *aoext;
    cudaGetSymbolAddress((void**)&cond_ptr, g_cond);
    cudaGetSymbolAddress((void**)&cext,  g_condext);
    cudaGetSymbolAddress((void**)&wcext, g_wcext);
    cudaGetSymbolAddress((void**)&woext, g_woext);
    cudaGetSymbolAddress((void**)&aoext, g_aoext);

    cudaFuncSetAttribute(gemm_hmma,
                         cudaFuncAttributeMaxDynamicSharedMemorySize, DSMEM);

    // splits
    {
        int n = NBATCH * SQ * CDIM;
        split_pack<<<n / 4 / 256, 256>>>(condition, cext, CDIM, n);
        n = EDIM * CDIM;
        split_pack<<<n / 4 / 256, 256>>>(Wc, wcext, CDIM, n);
        n = EDIM * EDIM;
        split_pack<<<n / 4 / 256, 256>>>(Wo, woext, EDIM, n);
    }

    // 1) cond = condition @ Wc^T + bc : M=8192, N=1024, K=512 (K3=1536)
    {
        dim3 grid(EDIM / BN, (NBATCH * SQ) / BM);
        gemm_hmma<<<grid, 256, DSMEM>>>(cext, wcext, bc, cond_ptr,
                                        NBATCH * SQ, EDIM, CDIM);
    }

    // 2) attention -> g_aoext (bf16 [hi|lo])
    attn_kernel<<<NBATCH * SKV, 256>>>(queries, keys, values, mask);

    // 3) out = attout @ Wo^T + bo : M=16384, N=1024, K=1024 (K3=3072)
    {
        dim3 grid(EDIM / BN, (NBATCH * SKV) / BM);
        gemm_hmma<<<grid, 256, DSMEM>>>(aoext, woext, bo, out,
                                        NBATCH * SKV, EDIM, EDIM);
    }
}

// round 8
// speedup vs baseline: 1.1239x; 1.1239x over previous
#include <cuda_runtime.h>
#include <cuda_bf16.h>
#include <stdint.h>
#include <math.h>

#define NBATCH 4
#define SQ    2048
#define SKV   4096
#define EDIM  1024
#define CDIM  512
#define HEADS 16
#define HDIM  64

// ---------------------------------------------------------------------------
// Static device scratch. Split operands stored [hi | lo] (width 2K).
// Logical GEMM runs K3=3K with per-chunk source remap:
//   A terms: hi, hi, lo     B terms: hi, lo, hi
// => sum = A0B0 + A0B1 + A1B0  (Markidis split, err ~2^-18)
// ---------------------------------------------------------------------------
__device__ float         g_cond[(size_t)NBATCH * SQ * EDIM];
__device__ __nv_bfloat16 g_condext[(size_t)NBATCH * SQ * 2 * CDIM];
__device__ __nv_bfloat16 g_wcext[(size_t)EDIM * 2 * CDIM];
__device__ __nv_bfloat16 g_woext[(size_t)EDIM * 2 * EDIM];
__device__ __nv_bfloat16 g_aoext[(size_t)NBATCH * SKV * 2 * EDIM];

// ---------------------------------------------------------------------------
// PTX helpers
// ---------------------------------------------------------------------------
__device__ __forceinline__ uint32_t smem_u32(const void* p) {
    uint32_t a;
    asm("{ .reg .u64 t; cvta.to.shared.u64 t, %1; cvt.u32.u64 %0, t; }"
        : "=r"(a) : "l"(p));
    return a;
}

__device__ __forceinline__ void cp16(uint32_t dst, const void* src) {
    asm volatile("cp.async.cg.shared.global [%0], [%1], 16;\n" :: "r"(dst), "l"(src));
}

#define LDSM4(r, addr) \
    asm volatile("ldmatrix.sync.aligned.m8n8.x4.shared.b16 {%0,%1,%2,%3}, [%4];" \
        : "=r"((r)[0]), "=r"((r)[1]), "=r"((r)[2]), "=r"((r)[3]) : "r"(addr))

#define MMA16816(d, a, b) \
    asm volatile("mma.sync.aligned.m16n8k16.row.col.f32.bf16.bf16.f32 " \
        "{%0,%1,%2,%3}, {%4,%5,%6,%7}, {%8,%9}, {%0,%1,%2,%3};" \
        : "+f"((d)[0]), "+f"((d)[1]), "+f"((d)[2]), "+f"((d)[3]) \
        : "r"((a)[0]), "r"((a)[1]), "r"((a)[2]), "r"((a)[3]), \
          "r"((b)[0]), "r"((b)[1]))

// ---------------------------------------------------------------------------
// split: fp32 (M,K) -> bf16 (M,2K) as [hi | lo]
// ---------------------------------------------------------------------------
__global__ __launch_bounds__(256) void split_pack(
    const float* __restrict__ src, __nv_bfloat16* __restrict__ dst,
    int K, int n)
{
    int i = (blockIdx.x * blockDim.x + threadIdx.x) * 4;
    if (i >= n) return;
    int m = i / K, k = i % K;
    float4 v = *(const float4*)(src + i);
    float x[4] = {v.x, v.y, v.z, v.w};
    __nv_bfloat16 hi[4], lo[4];
    #pragma unroll
    for (int j = 0; j < 4; j++) {
        hi[j] = __float2bfloat16_rn(x[j]);
        lo[j] = __float2bfloat16_rn(x[j] - __bfloat162float(hi[j]));
    }
    size_t base = (size_t)m * 2 * K + k;
    *(uint2*)(dst + base)     = *(uint2*)hi;
    *(uint2*)(dst + base + K) = *(uint2*)lo;
}

// ---------------------------------------------------------------------------
// HMMA GEMM. BM=BN=128, BKC=64, 8 warps (32x64 warp tile), 3-stage cp.async.
// A-frags double-buffered across ks; B-frags per-ks in two halves so the
// second half's LDSM overlaps the first half's MMA burst. <=128 regs keeps
// 2 CTAs/SM. SMEM rows 144B: conflict-free ldmatrix.
// ---------------------------------------------------------------------------
#define BM 128
#define BN 128
#define BKC 64
#define AROW 144
#define ASTAGE (128 * AROW)       // 18432 B
#define STAGE  (2 * ASTAGE)       // 36864 B
#define NSTAGE 3
#define DSMEM  (NSTAGE * STAGE)   // 110592 B

__device__ __forceinline__ void gemm_issue(
    uint32_t s0, int slot, int c, int nc1, int K, int tid, int mBase, int nBase,
    const __nv_bfloat16* __restrict__ A, const __nv_bfloat16* __restrict__ B)
{
    // term schedule: A: hi,hi,lo   B: hi,lo,hi
    int k0A, k0B;
    if (c < nc1)          { k0A = c * BKC;                 k0B = c * BKC; }
    else if (c < 2 * nc1) { k0A = (c - nc1) * BKC;         k0B = K + (c - nc1) * BKC; }
    else                  { k0A = K + (c - 2 * nc1) * BKC; k0B = (c - 2 * nc1) * BKC; }

    const int K2 = 2 * K;
    uint32_t sA = s0 + slot * STAGE;
    uint32_t sB = sA + ASTAGE;
    #pragma unroll
    for (int i = 0; i < 4; i++) {
        int ch = tid + i * 256;          // 0..1023
        int r = ch >> 3, col = ch & 7;   // row, 16B-chunk within 128B
        cp16(sA + r * AROW + col * 16, A + (size_t)(mBase + r) * K2 + k0A + col * 8);
        cp16(sB + r * AROW + col * 16, B + (size_t)(nBase + r) * K2 + k0B + col * 8);
    }
    asm volatile("cp.async.commit_group;");
}

__device__ __forceinline__ void load_a(
    uint32_t sA, int ks, int wm, int lane, uint32_t af[2][4])
{
    #pragma unroll
    for (int mi = 0; mi < 2; mi++) {
        uint32_t addr = sA + (wm + mi * 16 + (lane & 15)) * AROW
                      + ks * 32 + (lane >> 4) * 16;
        LDSM4(af[mi], addr);
    }
}

// half h (0/1): loads B frags for ni = 4h .. 4h+3
__device__ __forceinline__ void load_b_half(
    uint32_t sB, int ks, int wn, int lane, int h, uint32_t bf[4][2])
{
    #pragma unroll
    for (int p2 = 0; p2 < 2; p2++) {
        int p = h * 2 + p2;
        int grp = lane >> 3, w = lane & 7;
        int nsel = p * 2 + (grp >> 1);
        uint32_t addr = sB + (wn + nsel * 8 + w) * AROW
                      + ks * 32 + (grp & 1) * 16;
        uint32_t r[4];
        LDSM4(r, addr);
        bf[p2 * 2][0]     = r[0];
        bf[p2 * 2][1]     = r[1];
        bf[p2 * 2 + 1][0] = r[2];
        bf[p2 * 2 + 1][1] = r[3];
    }
}

__global__ __launch_bounds__(256, 2) void gemm_hmma(
    const __nv_bfloat16* __restrict__ A, const __nv_bfloat16* __restrict__ B,
    const float* __restrict__ bias, float* __restrict__ C,
    int M, int N, int K)
{
    extern __shared__ char smem[];
    const int tid  = threadIdx.x;
    const int wid  = tid >> 5;
    const int lane = tid & 31;
    const int mBase = blockIdx.y * BM;
    const int nBase = blockIdx.x * BN;
    const int wm = (wid & 3) * 32;
    const int wn = (wid >> 2) * 64;

    const uint32_t s0 = smem_u32(smem);
    const int nc1 = K / BKC;
    const int NC = 3 * nc1;

    float acc[2][8][4];
    #pragma unroll
    for (int i = 0; i < 2; i++)
        #pragma unroll
        for (int j = 0; j < 8; j++)
            #pragma unroll
            for (int q = 0; q < 4; q++) acc[i][j][q] = 0.f;

    // prologue: two stages in flight, first ready, first A frags loaded
    gemm_issue(s0, 0, 0, nc1, K, tid, mBase, nBase, A, B);
    gemm_issue(s0, 1, 1, nc1, K, tid, mBase, nBase, A, B);
    asm volatile("cp.async.wait_group 1;");
    __syncthreads();

    uint32_t af[2][2][4];
    load_a(s0, 0, wm, lane, af[0]);

    int buf = 0;
    for (int c = 0; c < NC; c++) {
        uint32_t csA = s0 + (c % NSTAGE) * STAGE;
        uint32_t csB = csA + ASTAGE;
        #pragma unroll
        for (int ks = 0; ks < 4; ks++) {
            int nb = buf ^ 1;
            uint32_t bf0[4][2], bf1[4][2];
            load_b_half(csB, ks, wn, lane, 0, bf0);
            load_b_half(csB, ks, wn, lane, 1, bf1);

            if (ks < 3) {
                load_a(csA, ks + 1, wm, lane, af[nb]);
            } else {
                if (c + 2 < NC)
                    gemm_issue(s0, (c + 2) % NSTAGE, c + 2, nc1, K, tid,
                               mBase, nBase, A, B);
                else
                    asm volatile("cp.async.commit_group;");
                if (c + 1 < NC) {
                    asm volatile("cp.async.wait_group 1;");
                    __syncthreads();
                    uint32_t nA = s0 + ((c + 1) % NSTAGE) * STAGE;
                    load_a(nA, 0, wm, lane, af[nb]);
                }
            }

            #pragma unroll
            for (int mi = 0; mi < 2; mi++)
                #pragma unroll
                for (int ni = 0; ni < 4; ni++)
                    MMA16816(acc[mi][ni], af[buf][mi], bf0[ni]);
            #pragma unroll
            for (int mi = 0; mi < 2; mi++)
                #pragma unroll
                for (int ni = 0; ni < 4; ni++)
                    MMA16816(acc[mi][ni + 4], af[buf][mi], bf1[ni]);

            buf = nb;
        }
    }

    const int g = lane >> 2, tg = lane & 3;
    #pragma unroll
    for (int mi = 0; mi < 2; mi++) {
        int row0 = mBase + wm + mi * 16 + g;
        #pragma unroll
        for (int ni = 0; ni < 8; ni++) {
            int col = nBase + wn + ni * 8 + tg * 2;
            float b0 = __ldg(bias + col), b1 = __ldg(bias + col + 1);
            float2 v0 = make_float2(acc[mi][ni][0] + b0, acc[mi][ni][1] + b1);
            float2 v1 = make_float2(acc[mi][ni][2] + b0, acc[mi][ni][3] + b1);
            *(float2*)(C + (size_t)row0 * N + col) = v0;
            *(float2*)(C + (size_t)(row0 + 8) * N + col) = v1;
        }
    }
}

// ---------------------------------------------------------------------------
// Per-position heads-attention (fp32 exact). Writes bf16 [hi | lo] rows.
// ---------------------------------------------------------------------------
__global__ __launch_bounds__(256) void attn_kernel(
    const float* __restrict__ queries, const float* __restrict__ keys,
    const float* __restrict__ values, const int* __restrict__ mask)
{
    __shared__ float cq[1024];
    __shared__ float kT[64 * 17];
    __shared__ float vv[1024];
    __shared__ float sc[16][16];

    const int pos = blockIdx.x;
    const int n = pos >> 12;
    const int t = pos & (SKV - 1);
    const int tid = threadIdx.x;

    const float* cqrow = (t & 1)
        ? (g_cond  + (size_t)(n * SQ + (t >> 1)) * EDIM)
        : (queries + (size_t)(n * SQ + (t >> 1)) * EDIM);
    const float* krow = keys   + (size_t)pos * EDIM;
    const float* vrow = values + (size_t)pos * EDIM;

    ((float4*)cq)[tid] = ((const float4*)cqrow)[tid];
    ((float4*)vv)[tid] = ((const float4*)vrow)[tid];
    {
        float4 kv = ((const float4*)krow)[tid];
        int gidx = tid * 4;
        #pragma unroll
        for (int i = 0; i < 4; i++) {
            int gg = gidx + i;
            kT[(gg & 63) * 17 + (gg >> 6)] = (&kv.x)[i];
        }
    }
    __syncthreads();

    const int h = tid >> 4;
    const int e = tid & 15;
    float s = 0.f;
    #pragma unroll
    for (int d = 0; d < HDIM; d++)
        s += cq[h * HDIM + d] * kT[d * 17 + e];
    s *= 0.125f;

    if (mask[(size_t)pos * (HEADS * HEADS) + h * 16 + e] == 0) s = -1e20f;
    sc[h][e] = s;
    __syncthreads();

    float mx = -INFINITY;
    #pragma unroll
    for (int j = 0; j < 16; j++) mx = fmaxf(mx, sc[h][j]);
    float denom = 0.f;
    #pragma unroll
    for (int j = 0; j < 16; j++) denom += expf(sc[h][j] - mx);
    float p = expf(s - mx) / denom;
    __syncthreads();
    sc[h][e] = p;
    __syncthreads();

    const int obase = tid * 4;
    const int oh = obase >> 6;
    const int od = obase & 63;
    float a0 = 0.f, a1 = 0.f, a2 = 0.f, a3 = 0.f;
    #pragma unroll
    for (int j = 0; j < 16; j++) {
        float a = sc[oh][j];
        const float* vj = vv + j * HDIM + od;
        a0 += a * vj[0];
        a1 += a * vj[1];
        a2 += a * vj[2];
        a3 += a * vj[3];
    }

    float o[4] = {a0, a1, a2, a3};
    __nv_bfloat16 hi[4], lo[4];
    #pragma unroll
    for (int j = 0; j < 4; j++) {
        hi[j] = __float2bfloat16_rn(o[j]);
        lo[j] = __float2bfloat16_rn(o[j] - __bfloat162float(hi[j]));
    }
    size_t base = (size_t)pos * (2 * EDIM) + obase;
    *(uint2*)(g_aoext + base)        = *(uint2*)hi;
    *(uint2*)(g_aoext + base + EDIM) = *(uint2*)lo;
}

// ---------------------------------------------------------------------------
// Launch
// ---------------------------------------------------------------------------
extern "C" void kernel_launch(void* const* d_in, const int* in_sizes, int n_in,
                              void* d_out, int out_size)
{
    const float* values    = (const float*)d_in[0];
    const float* keys      = (const float*)d_in[1];
    const float* queries   = (const float*)d_in[2];
    const int*   mask      = (const int*)  d_in[3];
    const float* condition = (const float*)d_in[4];
    const float* Wc        = (const float*)d_in[5];
    const float* bc        = (const float*)d_in[6];
    const float* Wo        = (const float*)d_in[7];
    const float* bo        = (const float*)d_in[8];
    float* out = (float*)d_out;

    float* cond_ptr;
    __nv_bfloat16 *cext, *wcext, *woext, *aoext;
    cudaGetSymbolAddress((void**)&cond_ptr, g_cond);
    cudaGetSymbolAddress((void**)&cext,  g_condext);
    cudaGetSymbolAddress((void**)&wcext, g_wcext);
    cudaGetSymbolAddress((void**)&woext, g_woext);
    cudaGetSymbolAddress((void**)&aoext, g_aoext);

    cudaFuncSetAttribute(gemm_hmma,
                         cudaFuncAttributeMaxDynamicSharedMemorySize, DSMEM);

    // splits
    {
        int n = NBATCH * SQ * CDIM;
        split_pack<<<n / 4 / 256, 256>>>(condition, cext, CDIM, n);
        n = EDIM * CDIM;
        split_pack<<<n / 4 / 256, 256>>>(Wc, wcext, CDIM, n);
        n = EDIM * EDIM;
        split_pack<<<n / 4 / 256, 256>>>(Wo, woext, EDIM, n);
    }

    // 1) cond = condition @ Wc^T + bc : M=8192, N=1024, K=512 (K3=1536)
    {
        dim3 grid(EDIM / BN, (NBATCH * SQ) / BM);
        gemm_hmma<<<grid, 256, DSMEM>>>(cext, wcext, bc, cond_ptr,
                                        NBATCH * SQ, EDIM, CDIM);
    }

    // 2) attention -> g_aoext (bf16 [hi|lo])
    attn_kernel<<<NBATCH * SKV, 256>>>(queries, keys, values, mask);

    // 3) out = attout @ Wo^T + bo : M=16384, N=1024, K=1024 (K3=3072)
    {
        dim3 grid(EDIM / BN, (NBATCH * SKV) / BM);
        gemm_hmma<<<grid, 256, DSMEM>>>(aoext, woext, bo, out,
                                        NBATCH * SKV, EDIM, EDIM);
    }
}

// round 9
// speedup vs baseline: 1.1307x; 1.0061x over previous
#include <cuda_runtime.h>
#include <cuda_bf16.h>
#include <stdint.h>
#include <math.h>

#define NBATCH 4
#define SQ    2048
#define SKV   4096
#define EDIM  1024
#define CDIM  512
#define HEADS 16
#define HDIM  64

// ---------------------------------------------------------------------------
// Static device scratch. Split operands stored [hi | lo] (width 2K).
// Logical GEMM runs K3=3K with per-chunk source remap:
//   A terms: hi, hi, lo     B terms: hi, lo, hi
// => sum = A0B0 + A0B1 + A1B0  (Markidis split, err ~2^-18)
// ---------------------------------------------------------------------------
__device__ float         g_cond[(size_t)NBATCH * SQ * EDIM];
__device__ __nv_bfloat16 g_condext[(size_t)NBATCH * SQ * 2 * CDIM];
__device__ __nv_bfloat16 g_wcext[(size_t)EDIM * 2 * CDIM];
__device__ __nv_bfloat16 g_woext[(size_t)EDIM * 2 * EDIM];
__device__ __nv_bfloat16 g_aoext[(size_t)NBATCH * SKV * 2 * EDIM];

// ---------------------------------------------------------------------------
// PTX helpers
// ---------------------------------------------------------------------------
__device__ __forceinline__ uint32_t smem_u32(const void* p) {
    uint32_t a;
    asm("{ .reg .u64 t; cvta.to.shared.u64 t, %1; cvt.u32.u64 %0, t; }"
        : "=r"(a) : "l"(p));
    return a;
}

__device__ __forceinline__ void cp16(uint32_t dst, const void* src) {
    asm volatile("cp.async.cg.shared.global [%0], [%1], 16;\n" :: "r"(dst), "l"(src));
}

#define LDSM4(r, addr) \
    asm volatile("ldmatrix.sync.aligned.m8n8.x4.shared.b16 {%0,%1,%2,%3}, [%4];" \
        : "=r"((r)[0]), "=r"((r)[1]), "=r"((r)[2]), "=r"((r)[3]) : "r"(addr))

#define MMA16816(d, a, b) \
    asm volatile("mma.sync.aligned.m16n8k16.row.col.f32.bf16.bf16.f32 " \
        "{%0,%1,%2,%3}, {%4,%5,%6,%7}, {%8,%9}, {%0,%1,%2,%3};" \
        : "+f"((d)[0]), "+f"((d)[1]), "+f"((d)[2]), "+f"((d)[3]) \
        : "r"((a)[0]), "r"((a)[1]), "r"((a)[2]), "r"((a)[3]), \
          "r"((b)[0]), "r"((b)[1]))

// ---------------------------------------------------------------------------
// split: fp32 (M,K) -> bf16 (M,2K) as [hi | lo]
// ---------------------------------------------------------------------------
__global__ __launch_bounds__(256) void split_pack(
    const float* __restrict__ src, __nv_bfloat16* __restrict__ dst,
    int K, int n)
{
    int i = (blockIdx.x * blockDim.x + threadIdx.x) * 4;
    if (i >= n) return;
    int m = i / K, k = i % K;
    float4 v = *(const float4*)(src + i);
    float x[4] = {v.x, v.y, v.z, v.w};
    __nv_bfloat16 hi[4], lo[4];
    #pragma unroll
    for (int j = 0; j < 4; j++) {
        hi[j] = __float2bfloat16_rn(x[j]);
        lo[j] = __float2bfloat16_rn(x[j] - __bfloat162float(hi[j]));
    }
    size_t base = (size_t)m * 2 * K + k;
    *(uint2*)(dst + base)     = *(uint2*)hi;
    *(uint2*)(dst + base + K) = *(uint2*)lo;
}

// ---------------------------------------------------------------------------
// HMMA GEMM. BM=BN=128, BKC=64. 128 threads, 4 warps, 64x64 warp tile
// (8 LDSM4 per 32 MMAs -> 1.5x better smem efficiency than 32x64).
// 3-stage cp.async, A-frags double-buffered across ks, B per-ks in halves.
// <=256 regs -> 2 CTAs/SM. SMEM rows 144B: conflict-free ldmatrix.
// ---------------------------------------------------------------------------
#define BM 128
#define BN 128
#define BKC 64
#define AROW 144
#define ASTAGE (128 * AROW)       // 18432 B
#define STAGE  (2 * ASTAGE)       // 36864 B
#define NSTAGE 3
#define DSMEM  (NSTAGE * STAGE)   // 110592 B

__device__ __forceinline__ void gemm_issue(
    uint32_t s0, int slot, int c, int nc1, int K, int tid, int mBase, int nBase,
    const __nv_bfloat16* __restrict__ A, const __nv_bfloat16* __restrict__ B)
{
    // term schedule: A: hi,hi,lo   B: hi,lo,hi
    int k0A, k0B;
    if (c < nc1)          { k0A = c * BKC;                 k0B = c * BKC; }
    else if (c < 2 * nc1) { k0A = (c - nc1) * BKC;         k0B = K + (c - nc1) * BKC; }
    else                  { k0A = K + (c - 2 * nc1) * BKC; k0B = (c - 2 * nc1) * BKC; }

    const int K2 = 2 * K;
    uint32_t sA = s0 + slot * STAGE;
    uint32_t sB = sA + ASTAGE;
    #pragma unroll
    for (int i = 0; i < 8; i++) {
        int ch = tid + i * 128;          // 0..1023
        int r = ch >> 3, col = ch & 7;   // row, 16B-chunk within 128B
        cp16(sA + r * AROW + col * 16, A + (size_t)(mBase + r) * K2 + k0A + col * 8);
        cp16(sB + r * AROW + col * 16, B + (size_t)(nBase + r) * K2 + k0B + col * 8);
    }
    asm volatile("cp.async.commit_group;");
}

__device__ __forceinline__ void load_a(
    uint32_t sA, int ks, int wm, int lane, uint32_t af[4][4])
{
    #pragma unroll
    for (int mi = 0; mi < 4; mi++) {
        uint32_t addr = sA + (wm + mi * 16 + (lane & 15)) * AROW
                      + ks * 32 + (lane >> 4) * 16;
        LDSM4(af[mi], addr);
    }
}

// half h (0/1): loads B frags for ni = 4h .. 4h+3
__device__ __forceinline__ void load_b_half(
    uint32_t sB, int ks, int wn, int lane, int h, uint32_t bf[4][2])
{
    #pragma unroll
    for (int p2 = 0; p2 < 2; p2++) {
        int p = h * 2 + p2;
        int grp = lane >> 3, w = lane & 7;
        int nsel = p * 2 + (grp >> 1);
        uint32_t addr = sB + (wn + nsel * 8 + w) * AROW
                      + ks * 32 + (grp & 1) * 16;
        uint32_t r[4];
        LDSM4(r, addr);
        bf[p2 * 2][0]     = r[0];
        bf[p2 * 2][1]     = r[1];
        bf[p2 * 2 + 1][0] = r[2];
        bf[p2 * 2 + 1][1] = r[3];
    }
}

__global__ __launch_bounds__(128, 2) void gemm_hmma(
    const __nv_bfloat16* __restrict__ A, const __nv_bfloat16* __restrict__ B,
    const float* __restrict__ bias, float* __restrict__ C,
    int M, int N, int K)
{
    extern __shared__ char smem[];
    const int tid  = threadIdx.x;
    const int wid  = tid >> 5;
    const int lane = tid & 31;
    const int mBase = blockIdx.y * BM;
    const int nBase = blockIdx.x * BN;
    const int wm = (wid & 1) * 64;
    const int wn = (wid >> 1) * 64;

    const uint32_t s0 = smem_u32(smem);
    const int nc1 = K / BKC;
    const int NC = 3 * nc1;

    float acc[4][8][4];
    #pragma unroll
    for (int i = 0; i < 4; i++)
        #pragma unroll
        for (int j = 0; j < 8; j++)
            #pragma unroll
            for (int q = 0; q < 4; q++) acc[i][j][q] = 0.f;

    // prologue: two stages in flight, first ready, first A frags loaded
    gemm_issue(s0, 0, 0, nc1, K, tid, mBase, nBase, A, B);
    gemm_issue(s0, 1, 1, nc1, K, tid, mBase, nBase, A, B);
    asm volatile("cp.async.wait_group 1;");
    __syncthreads();

    uint32_t af[2][4][4];
    load_a(s0, 0, wm, lane, af[0]);

    int buf = 0;
    for (int c = 0; c < NC; c++) {
        uint32_t csA = s0 + (c % NSTAGE) * STAGE;
        uint32_t csB = csA + ASTAGE;
        #pragma unroll
        for (int ks = 0; ks < 4; ks++) {
            int nb = buf ^ 1;
            uint32_t bf0[4][2], bf1[4][2];
            load_b_half(csB, ks, wn, lane, 0, bf0);
            load_b_half(csB, ks, wn, lane, 1, bf1);

            if (ks < 3) {
                load_a(csA, ks + 1, wm, lane, af[nb]);
            } else {
                if (c + 2 < NC)
                    gemm_issue(s0, (c + 2) % NSTAGE, c + 2, nc1, K, tid,
                               mBase, nBase, A, B);
                else
                    asm volatile("cp.async.commit_group;");
                if (c + 1 < NC) {
                    asm volatile("cp.async.wait_group 1;");
                    __syncthreads();
                    uint32_t nA = s0 + ((c + 1) % NSTAGE) * STAGE;
                    load_a(nA, 0, wm, lane, af[nb]);
                }
            }

            #pragma unroll
            for (int mi = 0; mi < 4; mi++)
                #pragma unroll
                for (int ni = 0; ni < 4; ni++)
                    MMA16816(acc[mi][ni], af[buf][mi], bf0[ni]);
            #pragma unroll
            for (int mi = 0; mi < 4; mi++)
                #pragma unroll
                for (int ni = 0; ni < 4; ni++)
                    MMA16816(acc[mi][ni + 4], af[buf][mi], bf1[ni]);

            buf = nb;
        }
    }

    const int g = lane >> 2, tg = lane & 3;
    #pragma unroll
    for (int mi = 0; mi < 4; mi++) {
        int row0 = mBase + wm + mi * 16 + g;
        #pragma unroll
        for (int ni = 0; ni < 8; ni++) {
            int col = nBase + wn + ni * 8 + tg * 2;
            float b0 = __ldg(bias + col), b1 = __ldg(bias + col + 1);
            float2 v0 = make_float2(acc[mi][ni][0] + b0, acc[mi][ni][1] + b1);
            float2 v1 = make_float2(acc[mi][ni][2] + b0, acc[mi][ni][3] + b1);
            *(float2*)(C + (size_t)row0 * N + col) = v0;
            *(float2*)(C + (size_t)(row0 + 8) * N + col) = v1;
        }
    }
}

// ---------------------------------------------------------------------------
// Per-position heads-attention (fp32 exact). Writes bf16 [hi | lo] rows.
// ---------------------------------------------------------------------------
__global__ __launch_bounds__(256) void attn_kernel(
    const float* __restrict__ queries, const float* __restrict__ keys,
    const float* __restrict__ values, const int* __restrict__ mask)
{
    __shared__ float cq[1024];
    __shared__ float kT[64 * 17];
    __shared__ float vv[1024];
    __shared__ float sc[16][16];

    const int pos = blockIdx.x;
    const int n = pos >> 12;
    const int t = pos & (SKV - 1);
    const int tid = threadIdx.x;

    const float* cqrow = (t & 1)
        ? (g_cond  + (size_t)(n * SQ + (t >> 1)) * EDIM)
        : (queries + (size_t)(n * SQ + (t >> 1)) * EDIM);
    const float* krow = keys   + (size_t)pos * EDIM;
    const float* vrow = values + (size_t)pos * EDIM;

    ((float4*)cq)[tid] = ((const float4*)cqrow)[tid];
    ((float4*)vv)[tid] = ((const float4*)vrow)[tid];
    {
        float4 kv = ((const float4*)krow)[tid];
        int gidx = tid * 4;
        #pragma unroll
        for (int i = 0; i < 4; i++) {
            int gg = gidx + i;
            kT[(gg & 63) * 17 + (gg >> 6)] = (&kv.x)[i];
        }
    }
    __syncthreads();

    const int h = tid >> 4;
    const int e = tid & 15;
    float s = 0.f;
    #pragma unroll
    for (int d = 0; d < HDIM; d++)
        s += cq[h * HDIM + d] * kT[d * 17 + e];
    s *= 0.125f;

    if (mask[(size_t)pos * (HEADS * HEADS) + h * 16 + e] == 0) s = -1e20f;
    sc[h][e] = s;
    __syncthreads();

    float mx = -INFINITY;
    #pragma unroll
    for (int j = 0; j < 16; j++) mx = fmaxf(mx, sc[h][j]);
    float denom = 0.f;
    #pragma unroll
    for (int j = 0; j < 16; j++) denom += expf(sc[h][j] - mx);
    float p = expf(s - mx) / denom;
    __syncthreads();
    sc[h][e] = p;
    __syncthreads();

    const int obase = tid * 4;
    const int oh = obase >> 6;
    const int od = obase & 63;
    float a0 = 0.f, a1 = 0.f, a2 = 0.f, a3 = 0.f;
    #pragma unroll
    for (int j = 0; j < 16; j++) {
        float a = sc[oh][j];
        const float* vj = vv + j * HDIM + od;
        a0 += a * vj[0];
        a1 += a * vj[1];
        a2 += a * vj[2];
        a3 += a * vj[3];
    }

    float o[4] = {a0, a1, a2, a3};
    __nv_bfloat16 hi[4], lo[4];
    #pragma unroll
    for (int j = 0; j < 4; j++) {
        hi[j] = __float2bfloat16_rn(o[j]);
        lo[j] = __float2bfloat16_rn(o[j] - __bfloat162float(hi[j]));
    }
    size_t base = (size_t)pos * (2 * EDIM) + obase;
    *(uint2*)(g_aoext + base)        = *(uint2*)hi;
    *(uint2*)(g_aoext + base + EDIM) = *(uint2*)lo;
}

// ---------------------------------------------------------------------------
// Launch
// ---------------------------------------------------------------------------
extern "C" void kernel_launch(void* const* d_in, const int* in_sizes, int n_in,
                              void* d_out, int out_size)
{
    const float* values    = (const float*)d_in[0];
    const float* keys      = (const float*)d_in[1];
    const float* queries   = (const float*)d_in[2];
    const int*   mask      = (const int*)  d_in[3];
    const float* condition = (const float*)d_in[4];
    const float* Wc        = (const float*)d_in[5];
    const float* bc        = (const float*)d_in[6];
    const float* Wo        = (const float*)d_in[7];
    const float* bo        = (const float*)d_in[8];
    float* out = (float*)d_out;

    float* cond_ptr;
    __nv_bfloat16 *cext, *wcext, *woext, *aoext;
    cudaGetSymbolAddress((void**)&cond_ptr, g_cond);
    cudaGetSymbolAddress((void**)&cext,  g_condext);
    cudaGetSymbolAddress((void**)&wcext, g_wcext);
    cudaGetSymbolAddress((void**)&woext, g_woext);
    cudaGetSymbolAddress((void**)&aoext, g_aoext);

    cudaFuncSetAttribute(gemm_hmma,
                         cudaFuncAttributeMaxDynamicSharedMemorySize, DSMEM);

    // splits
    {
        int n = NBATCH * SQ * CDIM;
        split_pack<<<n / 4 / 256, 256>>>(condition, cext, CDIM, n);
        n = EDIM * CDIM;
        split_pack<<<n / 4 / 256, 256>>>(Wc, wcext, CDIM, n);
        n = EDIM * EDIM;
        split_pack<<<n / 4 / 256, 256>>>(Wo, woext, EDIM, n);
    }

    // 1) cond = condition @ Wc^T + bc : M=8192, N=1024, K=512 (K3=1536)
    {
        dim3 grid(EDIM / BN, (NBATCH * SQ) / BM);
        gemm_hmma<<<grid, 128, DSMEM>>>(cext, wcext, bc, cond_ptr,
                                        NBATCH * SQ, EDIM, CDIM);
    }

    // 2) attention -> g_aoext (bf16 [hi|lo])
    attn_kernel<<<NBATCH * SKV, 256>>>(queries, keys, values, mask);

    // 3) out = attout @ Wo^T + bo : M=16384, N=1024, K=1024 (K3=3072)
    {
        dim3 grid(EDIM / BN, (NBATCH * SKV) / BM);
        gemm_hmma<<<grid, 128, DSMEM>>>(aoext, woext, bo, out,
                                        NBATCH * SKV, EDIM, EDIM);
    }
}

// round 10
// speedup vs baseline: 2.0347x; 1.7995x over previous
#include <cuda_runtime.h>
#include <cuda_fp16.h>
#include <stdint.h>
#include <math.h>

#define NBATCH 4
#define SQ    2048
#define SKV   4096
#define EDIM  1024
#define CDIM  512
#define HEADS 16
#define HDIM  64

// ---------------------------------------------------------------------------
// Static device scratch. Single-pass fp16 GEMM operands (10 mantissa bits;
// aggregate rel err ~2^-12.3 ~= 2e-4, 5x inside the 1e-3 tolerance).
// ---------------------------------------------------------------------------
__device__ float  g_cond[(size_t)NBATCH * SQ * EDIM];      // fp32 cond (attn input)
__device__ __half g_ch[(size_t)NBATCH * SQ * CDIM];        // condition fp16
__device__ __half g_wch[(size_t)EDIM * CDIM];              // Wc fp16
__device__ __half g_woh[(size_t)EDIM * EDIM];              // Wo fp16
__device__ __half g_aoh[(size_t)NBATCH * SKV * EDIM];      // attn out fp16 (33MB)

// ---------------------------------------------------------------------------
// PTX helpers
// ---------------------------------------------------------------------------
__device__ __forceinline__ uint32_t smem_u32(const void* p) {
    uint32_t a;
    asm("{ .reg .u64 t; cvta.to.shared.u64 t, %1; cvt.u32.u64 %0, t; }"
        : "=r"(a) : "l"(p));
    return a;
}

__device__ __forceinline__ void cp16(uint32_t dst, const void* src) {
    asm volatile("cp.async.cg.shared.global [%0], [%1], 16;\n" :: "r"(dst), "l"(src));
}

#define LDSM4(r, addr) \
    asm volatile("ldmatrix.sync.aligned.m8n8.x4.shared.b16 {%0,%1,%2,%3}, [%4];" \
        : "=r"((r)[0]), "=r"((r)[1]), "=r"((r)[2]), "=r"((r)[3]) : "r"(addr))

#define MMA16816(d, a, b) \
    asm volatile("mma.sync.aligned.m16n8k16.row.col.f32.f16.f16.f32 " \
        "{%0,%1,%2,%3}, {%4,%5,%6,%7}, {%8,%9}, {%0,%1,%2,%3};" \
        : "+f"((d)[0]), "+f"((d)[1]), "+f"((d)[2]), "+f"((d)[3]) \
        : "r"((a)[0]), "r"((a)[1]), "r"((a)[2]), "r"((a)[3]), \
          "r"((b)[0]), "r"((b)[1]))

// ---------------------------------------------------------------------------
// convert: fp32 -> fp16
// ---------------------------------------------------------------------------
__global__ __launch_bounds__(256) void to_half(
    const float* __restrict__ src, __half* __restrict__ dst, int n)
{
    int i = (blockIdx.x * blockDim.x + threadIdx.x) * 4;
    if (i >= n) return;
    float4 v = *(const float4*)(src + i);
    __half2 p0 = __floats2half2_rn(v.x, v.y);
    __half2 p1 = __floats2half2_rn(v.z, v.w);
    *(__half2*)(dst + i)     = p0;
    *(__half2*)(dst + i + 2) = p1;
}

// ---------------------------------------------------------------------------
// HMMA fp16 GEMM: C[m][n] = sum_k A[m][k]*B[n][k] + bias[n]  (fp32 accum)
// BM=BN=128, BKC=64. 128 threads, 4 warps, 64x64 warp tile.
// 3-stage cp.async, A-frags double-buffered across ks, B per-ks in halves.
// SMEM rows 144B: stride 36 words == 4 mod 32 -> conflict-free ldmatrix.
// ---------------------------------------------------------------------------
#define BM 128
#define BN 128
#define BKC 64
#define AROW 144
#define ASTAGE (128 * AROW)       // 18432 B
#define STAGE  (2 * ASTAGE)       // 36864 B
#define NSTAGE 3
#define DSMEM  (NSTAGE * STAGE)   // 110592 B

__device__ __forceinline__ void gemm_issue(
    uint32_t s0, int slot, int c, int K, int tid, int mBase, int nBase,
    const __half* __restrict__ A, const __half* __restrict__ B)
{
    int k0 = c * BKC;
    uint32_t sA = s0 + slot * STAGE;
    uint32_t sB = sA + ASTAGE;
    #pragma unroll
    for (int i = 0; i < 8; i++) {
        int ch = tid + i * 128;          // 0..1023
        int r = ch >> 3, col = ch & 7;   // row, 16B-chunk within 128B
        cp16(sA + r * AROW + col * 16, A + (size_t)(mBase + r) * K + k0 + col * 8);
        cp16(sB + r * AROW + col * 16, B + (size_t)(nBase + r) * K + k0 + col * 8);
    }
    asm volatile("cp.async.commit_group;");
}

__device__ __forceinline__ void load_a(
    uint32_t sA, int ks, int wm, int lane, uint32_t af[4][4])
{
    #pragma unroll
    for (int mi = 0; mi < 4; mi++) {
        uint32_t addr = sA + (wm + mi * 16 + (lane & 15)) * AROW
                      + ks * 32 + (lane >> 4) * 16;
        LDSM4(af[mi], addr);
    }
}

// half h (0/1): loads B frags for ni = 4h .. 4h+3
__device__ __forceinline__ void load_b_half(
    uint32_t sB, int ks, int wn, int lane, int h, uint32_t bf[4][2])
{
    #pragma unroll
    for (int p2 = 0; p2 < 2; p2++) {
        int p = h * 2 + p2;
        int grp = lane >> 3, w = lane & 7;
        int nsel = p * 2 + (grp >> 1);
        uint32_t addr = sB + (wn + nsel * 8 + w) * AROW
                      + ks * 32 + (grp & 1) * 16;
        uint32_t r[4];
        LDSM4(r, addr);
        bf[p2 * 2][0]     = r[0];
        bf[p2 * 2][1]     = r[1];
        bf[p2 * 2 + 1][0] = r[2];
        bf[p2 * 2 + 1][1] = r[3];
    }
}

__global__ __launch_bounds__(128, 2) void gemm_hmma(
    const __half* __restrict__ A, const __half* __restrict__ B,
    const float* __restrict__ bias, float* __restrict__ C,
    int M, int N, int K)
{
    extern __shared__ char smem[];
    const int tid  = threadIdx.x;
    const int wid  = tid >> 5;
    const int lane = tid & 31;
    const int mBase = blockIdx.y * BM;
    const int nBase = blockIdx.x * BN;
    const int wm = (wid & 1) * 64;
    const int wn = (wid >> 1) * 64;

    const uint32_t s0 = smem_u32(smem);
    const int NC = K / BKC;

    float acc[4][8][4];
    #pragma unroll
    for (int i = 0; i < 4; i++)
        #pragma unroll
        for (int j = 0; j < 8; j++)
            #pragma unroll
            for (int q = 0; q < 4; q++) acc[i][j][q] = 0.f;

    // prologue: two stages in flight, first ready, first A frags loaded
    gemm_issue(s0, 0, 0, K, tid, mBase, nBase, A, B);
    gemm_issue(s0, 1, 1, K, tid, mBase, nBase, A, B);
    asm volatile("cp.async.wait_group 1;");
    __syncthreads();

    uint32_t af[2][4][4];
    load_a(s0, 0, wm, lane, af[0]);

    int buf = 0;
    for (int c = 0; c < NC; c++) {
        uint32_t csA = s0 + (c % NSTAGE) * STAGE;
        uint32_t csB = csA + ASTAGE;
        #pragma unroll
        for (int ks = 0; ks < 4; ks++) {
            int nb = buf ^ 1;
            uint32_t bf0[4][2], bf1[4][2];
            load_b_half(csB, ks, wn, lane, 0, bf0);
            load_b_half(csB, ks, wn, lane, 1, bf1);

            if (ks < 3) {
                load_a(csA, ks + 1, wm, lane, af[nb]);
            } else {
                if (c + 2 < NC)
                    gemm_issue(s0, (c + 2) % NSTAGE, c + 2, K, tid,
                               mBase, nBase, A, B);
                else
                    asm volatile("cp.async.commit_group;");
                if (c + 1 < NC) {
                    asm volatile("cp.async.wait_group 1;");
                    __syncthreads();
                    uint32_t nA = s0 + ((c + 1) % NSTAGE) * STAGE;
                    load_a(nA, 0, wm, lane, af[nb]);
                }
            }

            #pragma unroll
            for (int mi = 0; mi < 4; mi++)
                #pragma unroll
                for (int ni = 0; ni < 4; ni++)
                    MMA16816(acc[mi][ni], af[buf][mi], bf0[ni]);
            #pragma unroll
            for (int mi = 0; mi < 4; mi++)
                #pragma unroll
                for (int ni = 0; ni < 4; ni++)
                    MMA16816(acc[mi][ni + 4], af[buf][mi], bf1[ni]);

            buf = nb;
        }
    }

    const int g = lane >> 2, tg = lane & 3;
    #pragma unroll
    for (int mi = 0; mi < 4; mi++) {
        int row0 = mBase + wm + mi * 16 + g;
        #pragma unroll
        for (int ni = 0; ni < 8; ni++) {
            int col = nBase + wn + ni * 8 + tg * 2;
            float b0 = __ldg(bias + col), b1 = __ldg(bias + col + 1);
            float2 v0 = make_float2(acc[mi][ni][0] + b0, acc[mi][ni][1] + b1);
            float2 v1 = make_float2(acc[mi][ni][2] + b0, acc[mi][ni][3] + b1);
            *(float2*)(C + (size_t)row0 * N + col) = v0;
            *(float2*)(C + (size_t)(row0 + 8) * N + col) = v1;
        }
    }
}

// ---------------------------------------------------------------------------
// Per-position heads-attention (fp32 exact math). Writes fp16 rows.
// ---------------------------------------------------------------------------
__global__ __launch_bounds__(256) void attn_kernel(
    const float* __restrict__ queries, const float* __restrict__ keys,
    const float* __restrict__ values, const int* __restrict__ mask)
{
    __shared__ float cq[1024];
    __shared__ float kT[64 * 17];
    __shared__ float vv[1024];
    __shared__ float sc[16][16];

    const int pos = blockIdx.x;
    const int n = pos >> 12;
    const int t = pos & (SKV - 1);
    const int tid = threadIdx.x;

    const float* cqrow = (t & 1)
        ? (g_cond  + (size_t)(n * SQ + (t >> 1)) * EDIM)
        : (queries + (size_t)(n * SQ + (t >> 1)) * EDIM);
    const float* krow = keys   + (size_t)pos * EDIM;
    const float* vrow = values + (size_t)pos * EDIM;

    ((float4*)cq)[tid] = ((const float4*)cqrow)[tid];
    ((float4*)vv)[tid] = ((const float4*)vrow)[tid];
    {
        float4 kv = ((const float4*)krow)[tid];
        int gidx = tid * 4;
        #pragma unroll
        for (int i = 0; i < 4; i++) {
            int gg = gidx + i;
            kT[(gg & 63) * 17 + (gg >> 6)] = (&kv.x)[i];
        }
    }
    __syncthreads();

    const int h = tid >> 4;
    const int e = tid & 15;
    float s = 0.f;
    #pragma unroll
    for (int d = 0; d < HDIM; d++)
        s += cq[h * HDIM + d] * kT[d * 17 + e];
    s *= 0.125f;

    if (mask[(size_t)pos * (HEADS * HEADS) + h * 16 + e] == 0) s = -1e20f;
    sc[h][e] = s;
    __syncthreads();

    float mx = -INFINITY;
    #pragma unroll
    for (int j = 0; j < 16; j++) mx = fmaxf(mx, sc[h][j]);
    float denom = 0.f;
    #pragma unroll
    for (int j = 0; j < 16; j++) denom += expf(sc[h][j] - mx);
    float p = expf(s - mx) / denom;
    __syncthreads();
    sc[h][e] = p;
    __syncthreads();

    const int obase = tid * 4;
    const int oh = obase >> 6;
    const int od = obase & 63;
    float a0 = 0.f, a1 = 0.f, a2 = 0.f, a3 = 0.f;
    #pragma unroll
    for (int j = 0; j < 16; j++) {
        float a = sc[oh][j];
        const float* vj = vv + j * HDIM + od;
        a0 += a * vj[0];
        a1 += a * vj[1];
        a2 += a * vj[2];
        a3 += a * vj[3];
    }

    size_t base = (size_t)pos * EDIM + obase;
    *(__half2*)(g_aoh + base)     = __floats2half2_rn(a0, a1);
    *(__half2*)(g_aoh + base + 2) = __floats2half2_rn(a2, a3);
}

// ---------------------------------------------------------------------------
// Launch
// ---------------------------------------------------------------------------
extern "C" void kernel_launch(void* const* d_in, const int* in_sizes, int n_in,
                              void* d_out, int out_size)
{
    const float* values    = (const float*)d_in[0];
    const float* keys      = (const float*)d_in[1];
    const float* queries   = (const float*)d_in[2];
    const int*   mask      = (const int*)  d_in[3];
    const float* condition = (const float*)d_in[4];
    const float* Wc        = (const float*)d_in[5];
    const float* bc        = (const float*)d_in[6];
    const float* Wo        = (const float*)d_in[7];
    const float* bo        = (const float*)d_in[8];
    float* out = (float*)d_out;

    float* cond_ptr;
    __half *ch, *wch, *woh, *aoh;
    cudaGetSymbolAddress((void**)&cond_ptr, g_cond);
    cudaGetSymbolAddress((void**)&ch,  g_ch);
    cudaGetSymbolAddress((void**)&wch, g_wch);
    cudaGetSymbolAddress((void**)&woh, g_woh);
    cudaGetSymbolAddress((void**)&aoh, g_aoh);

    cudaFuncSetAttribute(gemm_hmma,
                         cudaFuncAttributeMaxDynamicSharedMemorySize, DSMEM);

    // converts
    {
        int n = NBATCH * SQ * CDIM;
        to_half<<<n / 4 / 256, 256>>>(condition, ch, n);
        n = EDIM * CDIM;
        to_half<<<n / 4 / 256, 256>>>(Wc, wch, n);
        n = EDIM * EDIM;
        to_half<<<n / 4 / 256, 256>>>(Wo, woh, n);
    }

    // 1) cond = condition @ Wc^T + bc : M=8192, N=1024, K=512
    {
        dim3 grid(EDIM / BN, (NBATCH * SQ) / BM);
        gemm_hmma<<<grid, 128, DSMEM>>>(ch, wch, bc, cond_ptr,
                                        NBATCH * SQ, EDIM, CDIM);
    }

    // 2) attention -> g_aoh (fp16)
    attn_kernel<<<NBATCH * SKV, 256>>>(queries, keys, values, mask);

    // 3) out = attout @ Wo^T + bo : M=16384, N=1024, K=1024
    {
        dim3 grid(EDIM / BN, (NBATCH * SKV) / BM);
        gemm_hmma<<<grid, 128, DSMEM>>>(aoh, woh, bo, out,
                                        NBATCH * SKV, EDIM, EDIM);
    }
}

// round 11
// speedup vs baseline: 2.1145x; 1.0392x over previous
#include <cuda_runtime.h>
#include <cuda_fp16.h>
#include <stdint.h>
#include <math.h>

#define NBATCH 4
#define SQ    2048
#define SKV   4096
#define EDIM  1024
#define CDIM  512
#define HEADS 16
#define HDIM  64

// ---------------------------------------------------------------------------
// Static device scratch. Single-pass fp16 GEMM operands (10 mantissa bits;
// aggregate rel err ~2e-4, measured 3.0e-4, inside the 1e-3 tolerance).
// ---------------------------------------------------------------------------
__device__ float  g_cond[(size_t)NBATCH * SQ * EDIM];      // fp32 cond (attn input)
__device__ __half g_ch[(size_t)NBATCH * SQ * CDIM];        // condition fp16
__device__ __half g_wch[(size_t)EDIM * CDIM];              // Wc fp16
__device__ __half g_woh[(size_t)EDIM * EDIM];              // Wo fp16
__device__ __half g_aoh[(size_t)NBATCH * SKV * EDIM];      // attn out fp16

// ---------------------------------------------------------------------------
// PTX helpers
// ---------------------------------------------------------------------------
__device__ __forceinline__ uint32_t smem_u32(const void* p) {
    uint32_t a;
    asm("{ .reg .u64 t; cvta.to.shared.u64 t, %1; cvt.u32.u64 %0, t; }"
        : "=r"(a) : "l"(p));
    return a;
}

__device__ __forceinline__ void cp16(uint32_t dst, const void* src) {
    asm volatile("cp.async.cg.shared.global [%0], [%1], 16;\n" :: "r"(dst), "l"(src));
}

#define LDSM4(r, addr) \
    asm volatile("ldmatrix.sync.aligned.m8n8.x4.shared.b16 {%0,%1,%2,%3}, [%4];" \
        : "=r"((r)[0]), "=r"((r)[1]), "=r"((r)[2]), "=r"((r)[3]) : "r"(addr))

#define MMA16816(d, a, b) \
    asm volatile("mma.sync.aligned.m16n8k16.row.col.f32.f16.f16.f32 " \
        "{%0,%1,%2,%3}, {%4,%5,%6,%7}, {%8,%9}, {%0,%1,%2,%3};" \
        : "+f"((d)[0]), "+f"((d)[1]), "+f"((d)[2]), "+f"((d)[3]) \
        : "r"((a)[0]), "r"((a)[1]), "r"((a)[2]), "r"((a)[3]), \
          "r"((b)[0]), "r"((b)[1]))

// ---------------------------------------------------------------------------
// convert: fp32 -> fp16
// ---------------------------------------------------------------------------
__global__ __launch_bounds__(256) void to_half(
    const float* __restrict__ src, __half* __restrict__ dst, int n)
{
    int i = (blockIdx.x * blockDim.x + threadIdx.x) * 4;
    if (i >= n) return;
    float4 v = *(const float4*)(src + i);
    __half2 p0 = __floats2half2_rn(v.x, v.y);
    __half2 p1 = __floats2half2_rn(v.z, v.w);
    *(__half2*)(dst + i)     = p0;
    *(__half2*)(dst + i + 2) = p1;
}

// ---------------------------------------------------------------------------
// HMMA fp16 GEMM: C[m][n] = sum_k A[m][k]*B[n][k] + bias[n]  (fp32 accum)
// BM=BN=128, BKC=64. 128 threads, 4 warps, 64x64 warp tile.
// 3-stage cp.async, A-frags double-buffered across ks, B per-ks in halves.
// SMEM rows 144B: stride 36 words == 4 mod 32 -> conflict-free ldmatrix.
// ---------------------------------------------------------------------------
#define BM 128
#define BN 128
#define BKC 64
#define AROW 144
#define ASTAGE (128 * AROW)       // 18432 B
#define STAGE  (2 * ASTAGE)       // 36864 B
#define NSTAGE 3
#define DSMEM  (NSTAGE * STAGE)   // 110592 B

__device__ __forceinline__ void gemm_issue(
    uint32_t s0, int slot, int c, int K, int tid, int mBase, int nBase,
    const __half* __restrict__ A, const __half* __restrict__ B)
{
    int k0 = c * BKC;
    uint32_t sA = s0 + slot * STAGE;
    uint32_t sB = sA + ASTAGE;
    #pragma unroll
    for (int i = 0; i < 8; i++) {
        int ch = tid + i * 128;          // 0..1023
        int r = ch >> 3, col = ch & 7;   // row, 16B-chunk within 128B
        cp16(sA + r * AROW + col * 16, A + (size_t)(mBase + r) * K + k0 + col * 8);
        cp16(sB + r * AROW + col * 16, B + (size_t)(nBase + r) * K + k0 + col * 8);
    }
    asm volatile("cp.async.commit_group;");
}

__device__ __forceinline__ void load_a(
    uint32_t sA, int ks, int wm, int lane, uint32_t af[4][4])
{
    #pragma unroll
    for (int mi = 0; mi < 4; mi++) {
        uint32_t addr = sA + (wm + mi * 16 + (lane & 15)) * AROW
                      + ks * 32 + (lane >> 4) * 16;
        LDSM4(af[mi], addr);
    }
}

// half h (0/1): loads B frags for ni = 4h .. 4h+3
__device__ __forceinline__ void load_b_half(
    uint32_t sB, int ks, int wn, int lane, int h, uint32_t bf[4][2])
{
    #pragma unroll
    for (int p2 = 0; p2 < 2; p2++) {
        int p = h * 2 + p2;
        int grp = lane >> 3, w = lane & 7;
        int nsel = p * 2 + (grp >> 1);
        uint32_t addr = sB + (wn + nsel * 8 + w) * AROW
                      + ks * 32 + (grp & 1) * 16;
        uint32_t r[4];
        LDSM4(r, addr);
        bf[p2 * 2][0]     = r[0];
        bf[p2 * 2][1]     = r[1];
        bf[p2 * 2 + 1][0] = r[2];
        bf[p2 * 2 + 1][1] = r[3];
    }
}

__global__ __launch_bounds__(128, 2) void gemm_hmma(
    const __half* __restrict__ A, const __half* __restrict__ B,
    const float* __restrict__ bias, float* __restrict__ C,
    int M, int N, int K)
{
    extern __shared__ char smem[];
    const int tid  = threadIdx.x;
    const int wid  = tid >> 5;
    const int lane = tid & 31;
    const int mBase = blockIdx.y * BM;
    const int nBase = blockIdx.x * BN;
    const int wm = (wid & 1) * 64;
    const int wn = (wid >> 1) * 64;

    const uint32_t s0 = smem_u32(smem);
    const int NC = K / BKC;

    float acc[4][8][4];
    #pragma unroll
    for (int i = 0; i < 4; i++)
        #pragma unroll
        for (int j = 0; j < 8; j++)
            #pragma unroll
            for (int q = 0; q < 4; q++) acc[i][j][q] = 0.f;

    gemm_issue(s0, 0, 0, K, tid, mBase, nBase, A, B);
    gemm_issue(s0, 1, 1, K, tid, mBase, nBase, A, B);
    asm volatile("cp.async.wait_group 1;");
    __syncthreads();

    uint32_t af[2][4][4];
    load_a(s0, 0, wm, lane, af[0]);

    int buf = 0;
    for (int c = 0; c < NC; c++) {
        uint32_t csA = s0 + (c % NSTAGE) * STAGE;
        uint32_t csB = csA + ASTAGE;
        #pragma unroll
        for (int ks = 0; ks < 4; ks++) {
            int nb = buf ^ 1;
            uint32_t bf0[4][2], bf1[4][2];
            load_b_half(csB, ks, wn, lane, 0, bf0);
            load_b_half(csB, ks, wn, lane, 1, bf1);

            if (ks < 3) {
                load_a(csA, ks + 1, wm, lane, af[nb]);
            } else {
                if (c + 2 < NC)
                    gemm_issue(s0, (c + 2) % NSTAGE, c + 2, K, tid,
                               mBase, nBase, A, B);
                else
                    asm volatile("cp.async.commit_group;");
                if (c + 1 < NC) {
                    asm volatile("cp.async.wait_group 1;");
                    __syncthreads();
                    uint32_t nA = s0 + ((c + 1) % NSTAGE) * STAGE;
                    load_a(nA, 0, wm, lane, af[nb]);
                }
            }

            #pragma unroll
            for (int mi = 0; mi < 4; mi++)
                #pragma unroll
                for (int ni = 0; ni < 4; ni++)
                    MMA16816(acc[mi][ni], af[buf][mi], bf0[ni]);
            #pragma unroll
            for (int mi = 0; mi < 4; mi++)
                #pragma unroll
                for (int ni = 0; ni < 4; ni++)
                    MMA16816(acc[mi][ni + 4], af[buf][mi], bf1[ni]);

            buf = nb;
        }
    }

    const int g = lane >> 2, tg = lane & 3;
    #pragma unroll
    for (int mi = 0; mi < 4; mi++) {
        int row0 = mBase + wm + mi * 16 + g;
        #pragma unroll
        for (int ni = 0; ni < 8; ni++) {
            int col = nBase + wn + ni * 8 + tg * 2;
            float b0 = __ldg(bias + col), b1 = __ldg(bias + col + 1);
            float2 v0 = make_float2(acc[mi][ni][0] + b0, acc[mi][ni][1] + b1);
            float2 v1 = make_float2(acc[mi][ni][2] + b0, acc[mi][ni][3] + b1);
            *(float2*)(C + (size_t)row0 * N + col) = v0;
            *(float2*)(C + (size_t)(row0 + 8) * N + col) = v1;
        }
    }
}

// ---------------------------------------------------------------------------
// Per-position heads-attention. Softmax via shfl over 16-lane groups:
// 1 expf/thread instead of 17 (kills the hidden MUFU bottleneck).
// Thread map: tid = h*16 + e; lanes with xor-mask < 16 stay in the same row.
// ---------------------------------------------------------------------------
__global__ __launch_bounds__(256) void attn_kernel(
    const float* __restrict__ queries, const float* __restrict__ keys,
    const float* __restrict__ values, const int* __restrict__ mask)
{
    __shared__ float cq[1024];
    __shared__ float kT[64 * 17];
    __shared__ float vv[1024];
    __shared__ float sc[16][16];

    const int pos = blockIdx.x;
    const int n = pos >> 12;
    const int t = pos & (SKV - 1);
    const int tid = threadIdx.x;

    const float* cqrow = (t & 1)
        ? (g_cond  + (size_t)(n * SQ + (t >> 1)) * EDIM)
        : (queries + (size_t)(n * SQ + (t >> 1)) * EDIM);
    const float* krow = keys   + (size_t)pos * EDIM;
    const float* vrow = values + (size_t)pos * EDIM;

    const int h = tid >> 4;
    const int e = tid & 15;

    // mask load issued early to overlap with smem staging
    const int mv = mask[(size_t)pos * (HEADS * HEADS) + h * 16 + e];

    ((float4*)cq)[tid] = ((const float4*)cqrow)[tid];
    ((float4*)vv)[tid] = ((const float4*)vrow)[tid];
    {
        float4 kv = ((const float4*)krow)[tid];
        int gidx = tid * 4;
        #pragma unroll
        for (int i = 0; i < 4; i++) {
            int gg = gidx + i;
            kT[(gg & 63) * 17 + (gg >> 6)] = (&kv.x)[i];
        }
    }
    __syncthreads();

    float s = 0.f;
    #pragma unroll
    for (int d = 0; d < HDIM; d++)
        s += cq[h * HDIM + d] * kT[d * 17 + e];
    s *= 0.125f;
    if (mv == 0) s = -1e20f;

    // group-of-16 softmax via butterfly shuffles (one expf per thread)
    float mx = s;
    #pragma unroll
    for (int m = 1; m < 16; m <<= 1)
        mx = fmaxf(mx, __shfl_xor_sync(0xffffffffu, mx, m));
    float pu = __expf(s - mx);
    float den = pu;
    #pragma unroll
    for (int m = 1; m < 16; m <<= 1)
        den += __shfl_xor_sync(0xffffffffu, den, m);
    sc[h][e] = pu / den;
    __syncthreads();

    const int obase = tid * 4;
    const int oh = obase >> 6;
    const int od = obase & 63;
    float a0 = 0.f, a1 = 0.f, a2 = 0.f, a3 = 0.f;
    #pragma unroll
    for (int j = 0; j < 16; j++) {
        float a = sc[oh][j];
        const float* vj = vv + j * HDIM + od;
        a0 += a * vj[0];
        a1 += a * vj[1];
        a2 += a * vj[2];
        a3 += a * vj[3];
    }

    size_t base = (size_t)pos * EDIM + obase;
    *(__half2*)(g_aoh + base)     = __floats2half2_rn(a0, a1);
    *(__half2*)(g_aoh + base + 2) = __floats2half2_rn(a2, a3);
}

// ---------------------------------------------------------------------------
// Launch
// ---------------------------------------------------------------------------
extern "C" void kernel_launch(void* const* d_in, const int* in_sizes, int n_in,
                              void* d_out, int out_size)
{
    const float* values    = (const float*)d_in[0];
    const float* keys      = (const float*)d_in[1];
    const float* queries   = (const float*)d_in[2];
    const int*   mask      = (const int*)  d_in[3];
    const float* condition = (const float*)d_in[4];
    const float* Wc        = (const float*)d_in[5];
    const float* bc        = (const float*)d_in[6];
    const float* Wo        = (const float*)d_in[7];
    const float* bo        = (const float*)d_in[8];
    float* out = (float*)d_out;

    float* cond_ptr;
    __half *ch, *wch, *woh, *aoh;
    cudaGetSymbolAddress((void**)&cond_ptr, g_cond);
    cudaGetSymbolAddress((void**)&ch,  g_ch);
    cudaGetSymbolAddress((void**)&wch, g_wch);
    cudaGetSymbolAddress((void**)&woh, g_woh);
    cudaGetSymbolAddress((void**)&aoh, g_aoh);

    cudaFuncSetAttribute(gemm_hmma,
                         cudaFuncAttributeMaxDynamicSharedMemorySize, DSMEM);

    // converts
    {
        int n = NBATCH * SQ * CDIM;
        to_half<<<n / 4 / 256, 256>>>(condition, ch, n);
        n = EDIM * CDIM;
        to_half<<<n / 4 / 256, 256>>>(Wc, wch, n);
        n = EDIM * EDIM;
        to_half<<<n / 4 / 256, 256>>>(Wo, woh, n);
    }

    // 1) cond = condition @ Wc^T + bc : M=8192, N=1024, K=512
    {
        dim3 grid(EDIM / BN, (NBATCH * SQ) / BM);
        gemm_hmma<<<grid, 128, DSMEM>>>(ch, wch, bc, cond_ptr,
                                        NBATCH * SQ, EDIM, CDIM);
    }

    // 2) attention -> g_aoh (fp16)
    attn_kernel<<<NBATCH * SKV, 256>>>(queries, keys, values, mask);

    // 3) out = attout @ Wo^T + bo : M=16384, N=1024, K=1024
    {
        dim3 grid(EDIM / BN, (NBATCH * SKV) / BM);
        gemm_hmma<<<grid, 128, DSMEM>>>(aoh, woh, bo, out,
                                        NBATCH * SKV, EDIM, EDIM);
    }
}